// round 4
// baseline (speedup 1.0000x reference)
#include <cuda_runtime.h>
#include <cstdint>

#define DIMIN 64
#define HID   170
#define C2    340
#define BATCH 4
#define HW    256

typedef unsigned long long f32x2_t;   // packed pair of fp32

// Intermediate buffer t = FFT-filtered projection, [4,340,256,256] fp32 (356MB scratch)
__device__ float g_t[(size_t)BATCH * C2 * HW * HW];

// ---------- packed f32x2 helpers ----------
__device__ __forceinline__ f32x2_t ffma2(f32x2_t a, f32x2_t b, f32x2_t c) {
    f32x2_t d;
    asm("fma.rn.f32x2 %0, %1, %2, %3;" : "=l"(d) : "l"(a), "l"(b), "l"(c));
    return d;
}
__device__ __forceinline__ f32x2_t dup2(float v) {
    f32x2_t d;
    asm("mov.b64 %0, {%1, %1};" : "=l"(d) : "f"(v));
    return d;
}
__device__ __forceinline__ void unpack2(f32x2_t v, float& lo, float& hi) {
    asm("mov.b64 {%0, %1}, %2;" : "=f"(lo), "=f"(hi) : "l"(v));
}

// ---------- unrolled 8-point complex FFT (sgn=-1 fwd, +1 inv, unnormalized) ----------
__device__ __forceinline__ void fft8(float* xr, float* xi, float sgn) {
    float tr, ti;
    // bit reversal: swap (1,4), (3,6)
    tr = xr[1]; xr[1] = xr[4]; xr[4] = tr;  ti = xi[1]; xi[1] = xi[4]; xi[4] = ti;
    tr = xr[3]; xr[3] = xr[6]; xr[6] = tr;  ti = xi[3]; xi[3] = xi[6]; xi[6] = ti;
    // stage 1
    #pragma unroll
    for (int i = 0; i < 8; i += 2) {
        float ar = xr[i], ai = xi[i], br = xr[i+1], bi = xi[i+1];
        xr[i] = ar + br; xi[i] = ai + bi; xr[i+1] = ar - br; xi[i+1] = ai - bi;
    }
    // stage 2
    #pragma unroll
    for (int i = 0; i < 8; i += 4) {
        { float ar = xr[i], ai = xi[i], br = xr[i+2], bi = xi[i+2];
          xr[i] = ar + br; xi[i] = ai + bi; xr[i+2] = ar - br; xi[i+2] = ai - bi; }
        { float ar = xr[i+1], ai = xi[i+1], br = xr[i+3], bi = xi[i+3];
          float wr = -sgn * bi, wi = sgn * br;
          xr[i+1] = ar + wr; xi[i+1] = ai + wi; xr[i+3] = ar - wr; xi[i+3] = ai - wi; }
    }
    // stage 3
    const float c = 0.70710678118654752f;
    { float ar = xr[0], ai = xi[0], br = xr[4], bi = xi[4];
      xr[0] = ar + br; xi[0] = ai + bi; xr[4] = ar - br; xi[4] = ai - bi; }
    { float ar = xr[1], ai = xi[1], br = xr[5], bi = xi[5];
      float wr = c * (br - sgn * bi), wi = c * (bi + sgn * br);
      xr[1] = ar + wr; xi[1] = ai + wi; xr[5] = ar - wr; xi[5] = ai - wi; }
    { float ar = xr[2], ai = xi[2], br = xr[6], bi = xi[6];
      float wr = -sgn * bi, wi = sgn * br;
      xr[2] = ar + wr; xi[2] = ai + wi; xr[6] = ar - wr; xi[6] = ai - wi; }
    { float ar = xr[3], ai = xi[3], br = xr[7], bi = xi[7];
      float wr = c * (-br - sgn * bi), wi = c * (-bi + sgn * br);
      xr[3] = ar + wr; xi[3] = ai + wi; xr[7] = ar - wr; xi[7] = ai - wi; }
}

// Apply rfft2 -> *filter/64 -> irfft2 to one channel patch (acc as 32 packed f32x2),
// write 8x8 result to g_t.
__device__ __forceinline__ void fft_filter_store(int oc, const f32x2_t* acc,
                                                 const float* __restrict__ filt,
                                                 int b, int ph, int pw) {
    float a[64];
    #pragma unroll
    for (int j = 0; j < 32; j++) unpack2(acc[j], a[2*j], a[2*j+1]);

    float re[8][5], im[8][5];
    // forward row rFFTs (axis -1)
    #pragma unroll
    for (int r = 0; r < 8; r++) {
        float xr[8], xi[8];
        #pragma unroll
        for (int c = 0; c < 8; c++) { xr[c] = a[r*8 + c]; xi[c] = 0.f; }
        fft8(xr, xi, -1.f);
        #pragma unroll
        for (int k = 0; k < 5; k++) { re[r][k] = xr[k]; im[r][k] = xi[k]; }
    }
    // column FFT (axis -2) + filter*(1/64) + inverse column FFT
    const float* fch = filt + oc * 40;
    #pragma unroll
    for (int k = 0; k < 5; k++) {
        float xr[8], xi[8];
        #pragma unroll
        for (int r = 0; r < 8; r++) { xr[r] = re[r][k]; xi[r] = im[r][k]; }
        fft8(xr, xi, -1.f);
        #pragma unroll
        for (int r = 0; r < 8; r++) {
            float f = __ldg(fch + r*5 + k) * (1.f / 64.f);
            xr[r] *= f; xi[r] *= f;
        }
        fft8(xr, xi, 1.f);
        #pragma unroll
        for (int r = 0; r < 8; r++) { re[r][k] = xr[r]; im[r][k] = xi[r]; }
    }
    // inverse row rFFTs (Hermitian reconstruction) + store
    float* ob = g_t + (((size_t)(b * C2 + oc) * HW + ph*8) * HW + pw*8);
    #pragma unroll
    for (int r = 0; r < 8; r++) {
        float xr[8], xi[8];
        #pragma unroll
        for (int k = 0; k < 5; k++) { xr[k] = re[r][k]; xi[k] = im[r][k]; }
        xr[5] = re[r][3]; xi[5] = -im[r][3];
        xr[6] = re[r][2]; xi[6] = -im[r][2];
        xr[7] = re[r][1]; xi[7] = -im[r][1];
        fft8(xr, xi, 1.f);
        float4 v0 = make_float4(xr[0], xr[1], xr[2], xr[3]);
        float4 v1 = make_float4(xr[4], xr[5], xr[6], xr[7]);
        *(float4*)(ob + (size_t)r * HW)     = v0;
        *(float4*)(ob + (size_t)r * HW + 4) = v1;
    }
}

// ================= Kernel A: project_in (64->340) + patch FFT filter =================
// grid (32,32,4) = (pw, ph, b), 176 threads, 2 output channels per thread.
#define KA_THREADS 176
#define SMEM_A (64*64*4 + C2*DIMIN*4)   // patch (16KB) + transposed W_in (87KB) = 103424B

__global__ void __launch_bounds__(KA_THREADS, 2)
kA(const float* __restrict__ x, const float* __restrict__ Win,
   const float* __restrict__ filt) {
    extern __shared__ float sm[];
    float* sX = sm;             // [ic][64 pix]
    float* sW = sm + 64 * 64;   // transposed: [ic][oc]

    const int t  = threadIdx.x;
    const int pw = blockIdx.x, ph = blockIdx.y, b = blockIdx.z;

    // load 8x8 patch for 64 input channels (1024 float4)
    for (int i = t; i < 1024; i += KA_THREADS) {
        int ic = i >> 4, rr = (i >> 1) & 7, half = i & 1;
        float4 v = *(const float4*)(x + (((size_t)(b * DIMIN + ic) * HW + ph*8 + rr) * HW + pw*8 + half*4));
        *(float4*)(sX + ic*64 + rr*8 + half*4) = v;
    }
    // load W_in transposed (coalesced global read, scattered smem write)
    for (int i = t; i < C2 * DIMIN; i += KA_THREADS) {
        int oc = i >> 6, ic = i & 63;
        sW[ic * C2 + oc] = Win[i];
    }
    __syncthreads();

    const int oc0 = t;
    const int oc1 = t + KA_THREADS;
    const bool has1 = (oc1 < C2);
    const int oc1c = has1 ? oc1 : 0;

    f32x2_t a0[32], a1[32];
    #pragma unroll
    for (int j = 0; j < 32; j++) { a0[j] = 0ull; a1[j] = 0ull; }

    const f32x2_t* sXd = (const f32x2_t*)sX;
    #pragma unroll 2
    for (int ic = 0; ic < 64; ic++) {
        f32x2_t w0 = dup2(sW[ic * C2 + oc0]);
        f32x2_t w1 = dup2(sW[ic * C2 + oc1c]);
        #pragma unroll
        for (int j = 0; j < 32; j++) {
            f32x2_t xv = sXd[ic * 32 + j];
            a0[j] = ffma2(w0, xv, a0[j]);
            a1[j] = ffma2(w1, xv, a1[j]);
        }
    }
    __syncthreads();  // everyone done reading sX/sW — safe to reuse smem

    // park oc1 accumulators in smem to bound register pressure
    f32x2_t* sSpill = (f32x2_t*)sm;   // [32][KA_THREADS]
    #pragma unroll
    for (int j = 0; j < 32; j++) sSpill[j * KA_THREADS + t] = a1[j];

    fft_filter_store(oc0, a0, filt, b, ph, pw);

    if (has1) {
        f32x2_t a1b[32];
        #pragma unroll
        for (int j = 0; j < 32; j++) a1b[j] = sSpill[j * KA_THREADS + t];
        fft_filter_store(oc1, a1b, filt, b, ph, pw);
    }
}

// ============ Kernel B: depthwise 3x3 + GELU gate + project_out (170->64) ============
// grid (16,16,4), 256 threads, one output pixel per thread, 17 chunks of 10 hidden ch.
#define SMEM_B (HID*64*4 + C2*9*4 + 20*324*4)   // 43520 + 12240 + 25920 = 81680B

__global__ void __launch_bounds__(256, 2)
kB(const float* __restrict__ Wdw, const float* __restrict__ Wout,
   float* __restrict__ out) {
    extern __shared__ float sm[];
    float* sWo = sm;                 // transposed: [hc][64 o] (read as f32x2 pairs)
    float* sDw = sm + HID * 64;      // [340*9]
    float* sT  = sDw + C2 * 9;       // [20][18*18]

    const int t  = threadIdx.x;
    const int tx = t & 15, ty = t >> 4;
    const int bx = blockIdx.x * 16, by = blockIdx.y * 16, b = blockIdx.z;

    for (int i = t; i < DIMIN * HID; i += 256) {
        int o = i / HID, hc = i % HID;
        sWo[hc * 64 + o] = Wout[i];
    }
    for (int i = t; i < C2 * 9; i += 256) sDw[i] = Wdw[i];

    f32x2_t acc[32];
    #pragma unroll
    for (int j = 0; j < 32; j++) acc[j] = 0ull;

    const f32x2_t* sWo2 = (const f32x2_t*)sWo;

    for (int cc = 0; cc < 17; cc++) {
        __syncthreads();  // protect sT reuse (first iter: also orders sWo/sDw)
        // halo tile load: 20 channels (10 gate-a + 10 gate-b) x 18x18, zero padded
        for (int i = t; i < 20 * 324; i += 256) {
            int s = i / 324, p = i % 324;
            int ly = p / 18, lx = p % 18;
            int ch = (s < 10) ? (cc * 10 + s) : (HID + cc * 10 + (s - 10));
            int gy = by - 1 + ly, gx = bx - 1 + lx;
            float v = 0.f;
            if (gy >= 0 && gy < HW && gx >= 0 && gx < HW)
                v = g_t[(((size_t)b * C2 + ch) * HW + gy) * HW + gx];
            sT[i] = v;
        }
        __syncthreads();

        #pragma unroll 2
        for (int c = 0; c < 10; c++) {
            int hc = cc * 10 + c;
            const float* w1 = sDw + hc * 9;
            const float* w2 = sDw + (hc + HID) * 9;
            const float* t1 = sT + c * 324 + ty * 18 + tx;
            const float* t2 = t1 + 10 * 324;
            float d1 = 0.f, d2 = 0.f;
            #pragma unroll
            for (int ky = 0; ky < 3; ky++)
                #pragma unroll
                for (int kx = 0; kx < 3; kx++) {
                    d1 = fmaf(w1[ky*3 + kx], t1[ky*18 + kx], d1);
                    d2 = fmaf(w2[ky*3 + kx], t2[ky*18 + kx], d2);
                }
            // exact GELU(d1) * d2
            float g = 0.5f * d1 * (1.f + erff(d1 * 0.70710678118654752f)) * d2;
            f32x2_t g2 = dup2(g);
            #pragma unroll
            for (int j = 0; j < 32; j++)
                acc[j] = ffma2(g2, sWo2[hc * 32 + j], acc[j]);
        }
    }

    float* ob = out + (((size_t)b * DIMIN) * HW + (by + ty)) * HW + (bx + tx);
    #pragma unroll
    for (int j = 0; j < 32; j++) {
        float lo, hi;
        unpack2(acc[j], lo, hi);
        ob[(size_t)(2*j)     * HW * HW] = lo;
        ob[(size_t)(2*j + 1) * HW * HW] = hi;
    }
}

// ======================== launch ========================
extern "C" void kernel_launch(void* const* d_in, const int* in_sizes, int n_in,
                              void* d_out, int out_size) {
    (void)in_sizes; (void)n_in; (void)out_size;
    const float* x    = (const float*)d_in[0];
    const float* Win  = (const float*)d_in[1];
    const float* Wdw  = (const float*)d_in[2];
    const float* filt = (const float*)d_in[3];
    const float* Wout = (const float*)d_in[4];
    float* out = (float*)d_out;

    cudaFuncSetAttribute(kA, cudaFuncAttributeMaxDynamicSharedMemorySize, SMEM_A);
    cudaFuncSetAttribute(kB, cudaFuncAttributeMaxDynamicSharedMemorySize, SMEM_B);

    kA<<<dim3(32, 32, BATCH), KA_THREADS, SMEM_A>>>(x, Win, filt);
    kB<<<dim3(16, 16, BATCH), 256, SMEM_B>>>(Wdw, Wout, out);
}

// round 5
// speedup vs baseline: 1.0372x; 1.0372x over previous
#include <cuda_runtime.h>
#include <cstdint>

#define DIMIN 64
#define HID   170
#define C2    340
#define BATCH 4
#define HW    256

typedef unsigned long long f32x2_t;   // packed pair of fp32

// Intermediate buffer t = FFT-filtered projection, [4,340,256,256] fp32 (356MB scratch)
__device__ float g_t[(size_t)BATCH * C2 * HW * HW];

// ---------- packed f32x2 helpers ----------
__device__ __forceinline__ f32x2_t ffma2(f32x2_t a, f32x2_t b, f32x2_t c) {
    f32x2_t d;
    asm("fma.rn.f32x2 %0, %1, %2, %3;" : "=l"(d) : "l"(a), "l"(b), "l"(c));
    return d;
}
__device__ __forceinline__ f32x2_t dup2(float v) {
    f32x2_t d;
    asm("mov.b64 %0, {%1, %1};" : "=l"(d) : "f"(v));
    return d;
}
__device__ __forceinline__ void unpack2(f32x2_t v, float& lo, float& hi) {
    asm("mov.b64 {%0, %1}, %2;" : "=f"(lo), "=f"(hi) : "l"(v));
}

// ---------- unrolled 8-point complex FFT (sgn=-1 fwd, +1 inv, unnormalized) ----------
__device__ __forceinline__ void fft8(float* xr, float* xi, float sgn) {
    float tr, ti;
    tr = xr[1]; xr[1] = xr[4]; xr[4] = tr;  ti = xi[1]; xi[1] = xi[4]; xi[4] = ti;
    tr = xr[3]; xr[3] = xr[6]; xr[6] = tr;  ti = xi[3]; xi[3] = xi[6]; xi[6] = ti;
    #pragma unroll
    for (int i = 0; i < 8; i += 2) {
        float ar = xr[i], ai = xi[i], br = xr[i+1], bi = xi[i+1];
        xr[i] = ar + br; xi[i] = ai + bi; xr[i+1] = ar - br; xi[i+1] = ai - bi;
    }
    #pragma unroll
    for (int i = 0; i < 8; i += 4) {
        { float ar = xr[i], ai = xi[i], br = xr[i+2], bi = xi[i+2];
          xr[i] = ar + br; xi[i] = ai + bi; xr[i+2] = ar - br; xi[i+2] = ai - bi; }
        { float ar = xr[i+1], ai = xi[i+1], br = xr[i+3], bi = xi[i+3];
          float wr = -sgn * bi, wi = sgn * br;
          xr[i+1] = ar + wr; xi[i+1] = ai + wi; xr[i+3] = ar - wr; xi[i+3] = ai - wi; }
    }
    const float c = 0.70710678118654752f;
    { float ar = xr[0], ai = xi[0], br = xr[4], bi = xi[4];
      xr[0] = ar + br; xi[0] = ai + bi; xr[4] = ar - br; xi[4] = ai - bi; }
    { float ar = xr[1], ai = xi[1], br = xr[5], bi = xi[5];
      float wr = c * (br - sgn * bi), wi = c * (bi + sgn * br);
      xr[1] = ar + wr; xi[1] = ai + wi; xr[5] = ar - wr; xi[5] = ai - wi; }
    { float ar = xr[2], ai = xi[2], br = xr[6], bi = xi[6];
      float wr = -sgn * bi, wi = sgn * br;
      xr[2] = ar + wr; xi[2] = ai + wi; xr[6] = ar - wr; xi[6] = ai - wi; }
    { float ar = xr[3], ai = xi[3], br = xr[7], bi = xi[7];
      float wr = c * (-br - sgn * bi), wi = c * (-bi + sgn * br);
      xr[3] = ar + wr; xi[3] = ai + wi; xr[7] = ar - wr; xi[7] = ai - wi; }
}

__device__ __forceinline__ void fft_filter_store(int oc, const f32x2_t* acc,
                                                 const float* __restrict__ filt,
                                                 int b, int ph, int pw) {
    float a[64];
    #pragma unroll
    for (int j = 0; j < 32; j++) unpack2(acc[j], a[2*j], a[2*j+1]);

    float re[8][5], im[8][5];
    #pragma unroll
    for (int r = 0; r < 8; r++) {
        float xr[8], xi[8];
        #pragma unroll
        for (int c = 0; c < 8; c++) { xr[c] = a[r*8 + c]; xi[c] = 0.f; }
        fft8(xr, xi, -1.f);
        #pragma unroll
        for (int k = 0; k < 5; k++) { re[r][k] = xr[k]; im[r][k] = xi[k]; }
    }
    const float* fch = filt + oc * 40;
    #pragma unroll
    for (int k = 0; k < 5; k++) {
        float xr[8], xi[8];
        #pragma unroll
        for (int r = 0; r < 8; r++) { xr[r] = re[r][k]; xi[r] = im[r][k]; }
        fft8(xr, xi, -1.f);
        #pragma unroll
        for (int r = 0; r < 8; r++) {
            float f = __ldg(fch + r*5 + k) * (1.f / 64.f);
            xr[r] *= f; xi[r] *= f;
        }
        fft8(xr, xi, 1.f);
        #pragma unroll
        for (int r = 0; r < 8; r++) { re[r][k] = xr[r]; im[r][k] = xi[r]; }
    }
    float* ob = g_t + (((size_t)(b * C2 + oc) * HW + ph*8) * HW + pw*8);
    #pragma unroll
    for (int r = 0; r < 8; r++) {
        float xr[8], xi[8];
        #pragma unroll
        for (int k = 0; k < 5; k++) { xr[k] = re[r][k]; xi[k] = im[r][k]; }
        xr[5] = re[r][3]; xi[5] = -im[r][3];
        xr[6] = re[r][2]; xi[6] = -im[r][2];
        xr[7] = re[r][1]; xi[7] = -im[r][1];
        fft8(xr, xi, 1.f);
        float4 v0 = make_float4(xr[0], xr[1], xr[2], xr[3]);
        float4 v1 = make_float4(xr[4], xr[5], xr[6], xr[7]);
        *(float4*)(ob + (size_t)r * HW)     = v0;
        *(float4*)(ob + (size_t)r * HW + 4) = v1;
    }
}

// ================= Kernel A: project_in (64->340) + patch FFT filter =================
#define KA_THREADS 176
#define SMEM_A (64*64*4 + C2*DIMIN*4)   // patch (16KB) + transposed W_in (87KB)

__global__ void __launch_bounds__(KA_THREADS, 2)
kA(const float* __restrict__ x, const float* __restrict__ Win,
   const float* __restrict__ filt) {
    extern __shared__ float sm[];
    float* sX = sm;             // [ic][64 pix]
    float* sW = sm + 64 * 64;   // transposed: [ic][oc]

    const int t  = threadIdx.x;
    const int pw = blockIdx.x, ph = blockIdx.y, b = blockIdx.z;

    for (int i = t; i < 1024; i += KA_THREADS) {
        int ic = i >> 4, rr = (i >> 1) & 7, half = i & 1;
        float4 v = *(const float4*)(x + (((size_t)(b * DIMIN + ic) * HW + ph*8 + rr) * HW + pw*8 + half*4));
        *(float4*)(sX + ic*64 + rr*8 + half*4) = v;
    }
    for (int i = t; i < C2 * DIMIN; i += KA_THREADS) {
        int oc = i >> 6, ic = i & 63;
        sW[ic * C2 + oc] = Win[i];
    }
    __syncthreads();

    const int oc0 = t;
    const int oc1 = t + KA_THREADS;
    const bool has1 = (oc1 < C2);
    const int oc1c = has1 ? oc1 : 0;

    f32x2_t a0[32], a1[32];
    #pragma unroll
    for (int j = 0; j < 32; j++) { a0[j] = 0ull; a1[j] = 0ull; }

    const ulonglong2* sX4 = (const ulonglong2*)sX;   // LDS.128 broadcasts: 16 per ic
    #pragma unroll 2
    for (int ic = 0; ic < 64; ic++) {
        f32x2_t w0 = dup2(sW[ic * C2 + oc0]);
        f32x2_t w1 = dup2(sW[ic * C2 + oc1c]);
        #pragma unroll
        for (int j = 0; j < 16; j++) {
            ulonglong2 xv = sX4[ic * 16 + j];
            a0[2*j]   = ffma2(w0, xv.x, a0[2*j]);
            a0[2*j+1] = ffma2(w0, xv.y, a0[2*j+1]);
            a1[2*j]   = ffma2(w1, xv.x, a1[2*j]);
            a1[2*j+1] = ffma2(w1, xv.y, a1[2*j+1]);
        }
    }
    __syncthreads();

    f32x2_t* sSpill = (f32x2_t*)sm;   // [32][KA_THREADS]
    #pragma unroll
    for (int j = 0; j < 32; j++) sSpill[j * KA_THREADS + t] = a1[j];

    fft_filter_store(oc0, a0, filt, b, ph, pw);

    if (has1) {
        f32x2_t a1b[32];
        #pragma unroll
        for (int j = 0; j < 32; j++) a1b[j] = sSpill[j * KA_THREADS + t];
        fft_filter_store(oc1, a1b, filt, b, ph, pw);
    }
}

// ============ Kernel B: depthwise 3x3 + GELU gate + project_out (170->64) ============
// grid (16,16,4), 256 threads, 16x16 pixel tile, 17 chunks of 10 hidden channels.
// Per chunk: phase B computes gate product g -> sG staging; phase C does a
// register-tiled 256px x 64out x 10k GEMM (thread = 8px x 8out, pixel-pair f32x2).
#define SG_OFF   (HID*64 + C2*9 + 20*324)            // floats
#define SMEM_B   ((SG_OFF + 10*256) * 4)             // 91920 bytes

__global__ void __launch_bounds__(256, 2)
kB(const float* __restrict__ Wdw, const float* __restrict__ Wout,
   float* __restrict__ out) {
    extern __shared__ float sm[];
    float* sWo = sm;                 // transposed: [hc][64 o]
    float* sDw = sm + HID * 64;      // [340*9]
    float* sT  = sDw + C2 * 9;       // [20][18*18]
    float* sG  = sm + SG_OFF;        // [10][256]

    const int t  = threadIdx.x;
    const int tx = t & 15, ty = t >> 4;
    const int bx = blockIdx.x * 16, by = blockIdx.y * 16, b = blockIdx.z;

    // GEMM-phase thread mapping: warp = output group of 8, lane = pixel group of 8
    const int outg = t >> 5;         // 0..7
    const int pxg  = t & 31;         // 0..31
    const int p0   = pxg * 8;        // first pixel of this thread's 8

    for (int i = t; i < DIMIN * HID; i += 256) {
        int o = i / HID, hc = i % HID;
        sWo[hc * 64 + o] = Wout[i];
    }
    for (int i = t; i < C2 * 9; i += 256) sDw[i] = Wdw[i];

    // acc[o][pp]: 8 output channels x 4 pixel-pairs
    f32x2_t acc[8][4];
    #pragma unroll
    for (int o = 0; o < 8; o++)
        #pragma unroll
        for (int pp = 0; pp < 4; pp++) acc[o][pp] = 0ull;

    for (int cc = 0; cc < 17; cc++) {
        __syncthreads();  // sT safe to overwrite (prev B done); first iter: orders sWo/sDw
        // halo tile load: 20 channels (10 gate-a + 10 gate-b) x 18x18, zero padded
        for (int i = t; i < 20 * 324; i += 256) {
            int s = i / 324, p = i % 324;
            int ly = p / 18, lx = p % 18;
            int ch = (s < 10) ? (cc * 10 + s) : (HID + cc * 10 + (s - 10));
            int gy = by - 1 + ly, gx = bx - 1 + lx;
            float v = 0.f;
            if (gy >= 0 && gy < HW && gx >= 0 && gx < HW)
                v = g_t[(((size_t)b * C2 + ch) * HW + gy) * HW + gx];
            sT[i] = v;
        }
        __syncthreads();

        // -------- phase B: dw conv + exact GELU gate, stage g to sG --------
        #pragma unroll 2
        for (int c = 0; c < 10; c++) {
            int hc = cc * 10 + c;
            const float* w1 = sDw + hc * 9;
            const float* w2 = sDw + (hc + HID) * 9;
            const float* t1 = sT + c * 324 + ty * 18 + tx;
            const float* t2 = t1 + 10 * 324;
            float d1 = 0.f, d2 = 0.f;
            #pragma unroll
            for (int ky = 0; ky < 3; ky++)
                #pragma unroll
                for (int kx = 0; kx < 3; kx++) {
                    d1 = fmaf(w1[ky*3 + kx], t1[ky*18 + kx], d1);
                    d2 = fmaf(w2[ky*3 + kx], t2[ky*18 + kx], d2);
                }
            float g = 0.5f * d1 * (1.f + erff(d1 * 0.70710678118654752f)) * d2;
            sG[c * 256 + t] = g;
        }
        __syncthreads();

        // -------- phase C: projection GEMM update (k = 10) --------
        #pragma unroll
        for (int c = 0; c < 10; c++) {
            int hc = cc * 10 + c;
            // 8 gate values for this thread's pixels (2 x LDS.128, per-lane distinct)
            const ulonglong2* gp = (const ulonglong2*)(sG + c * 256 + p0);
            ulonglong2 gv0 = gp[0], gv1 = gp[1];
            // 8 weights for this warp's output group (2 x LDS.128 broadcast)
            const float4* wp = (const float4*)(sWo + hc * 64 + outg * 8);
            float4 w0 = wp[0], w1 = wp[1];
            f32x2_t wd[8];
            wd[0] = dup2(w0.x); wd[1] = dup2(w0.y); wd[2] = dup2(w0.z); wd[3] = dup2(w0.w);
            wd[4] = dup2(w1.x); wd[5] = dup2(w1.y); wd[6] = dup2(w1.z); wd[7] = dup2(w1.w);
            #pragma unroll
            for (int o = 0; o < 8; o++) {
                acc[o][0] = ffma2(wd[o], gv0.x, acc[o][0]);
                acc[o][1] = ffma2(wd[o], gv0.y, acc[o][1]);
                acc[o][2] = ffma2(wd[o], gv1.x, acc[o][2]);
                acc[o][3] = ffma2(wd[o], gv1.y, acc[o][3]);
            }
        }
    }

    // -------- store: thread owns outputs (outg*8..+7) x pixels (p0..p0+7) --------
    const int py  = p0 >> 4;        // tile row
    const int px0 = p0 & 15;        // 0 or 8
    #pragma unroll
    for (int o = 0; o < 8; o++) {
        int oc = outg * 8 + o;
        float v[8];
        #pragma unroll
        for (int pp = 0; pp < 4; pp++) unpack2(acc[o][pp], v[2*pp], v[2*pp+1]);
        float* ob = out + (((size_t)(b * DIMIN + oc)) * HW + (by + py)) * HW + (bx + px0);
        *(float4*)(ob)     = make_float4(v[0], v[1], v[2], v[3]);
        *(float4*)(ob + 4) = make_float4(v[4], v[5], v[6], v[7]);
    }
}

// ======================== launch ========================
extern "C" void kernel_launch(void* const* d_in, const int* in_sizes, int n_in,
                              void* d_out, int out_size) {
    (void)in_sizes; (void)n_in; (void)out_size;
    const float* x    = (const float*)d_in[0];
    const float* Win  = (const float*)d_in[1];
    const float* Wdw  = (const float*)d_in[2];
    const float* filt = (const float*)d_in[3];
    const float* Wout = (const float*)d_in[4];
    float* out = (float*)d_out;

    cudaFuncSetAttribute(kA, cudaFuncAttributeMaxDynamicSharedMemorySize, SMEM_A);
    cudaFuncSetAttribute(kB, cudaFuncAttributeMaxDynamicSharedMemorySize, SMEM_B);

    kA<<<dim3(32, 32, BATCH), KA_THREADS, SMEM_A>>>(x, Win, filt);
    kB<<<dim3(16, 16, BATCH), 256, SMEM_B>>>(Wdw, Wout, out);
}